// round 2
// baseline (speedup 1.0000x reference)
#include <cuda_runtime.h>

#define NN 100000
#define NE 3200000

// ---------------- scratch (static __device__ arrays; no allocation) --------
__device__ int   g_is64;
__device__ int   g_deg [NN];
__device__ float g_dinv[NN];
__device__ float g_g1  [NN * 16];   // dinv * (x @ W1)
__device__ float g_acc1[NN * 16];   // edge-aggregated g1
__device__ float g_g2  [NN * 32];   // dinv * (relu(out1) @ W2)

// vectorized fp32 reduction to global (sm_90+): 4 floats, no return value
__device__ __forceinline__ void red4(float* a, float4 v) {
    asm volatile("red.global.add.v4.f32 [%0], {%1,%2,%3,%4};"
                 :: "l"(a), "f"(v.x), "f"(v.y), "f"(v.z), "f"(v.w)
                 : "memory");
}

// ---------------- dtype detection -----------------------------------------
// edge_index values are in [0, 100000); if stored as int64 (little-endian),
// every odd int32 word is 0. For int32 data, 4096 random values in
// [0,100000) being all < 65536 has probability ~(0.655)^4096 ~= 0.
__global__ void detect_kernel(const int* __restrict__ e) {
    __shared__ int flag;
    if (threadIdx.x == 0) flag = 0;
    __syncthreads();
    int v = 0;
    for (int i = threadIdx.x; i < 4096; i += 1024) v |= e[2 * i + 1];
    if (v) atomicOr(&flag, 1);
    __syncthreads();
    if (threadIdx.x == 0) g_is64 = (flag == 0);
}

// ---------------- zero scratch + output ------------------------------------
__global__ void zero_kernel(float* __restrict__ out) {
    int i = blockIdx.x * blockDim.x + threadIdx.x;
    if (i < NN * 32) out[i] = 0.f;
    if (i < NN * 16) g_acc1[i] = 0.f;
    if (i < NN)      g_deg[i] = 0;
}

// ---------------- degree (in-degree from dst column) -----------------------
__global__ void __launch_bounds__(256) deg_kernel(const int* __restrict__ e) {
    int i = blockIdx.x * blockDim.x + threadIdx.x;
    if (i >= NE) return;
    int is64 = g_is64;
    long long off = is64 ? (2LL * NE + 2LL * i) : ((long long)NE + i);
    atomicAdd(&g_deg[e[off]], 1);
}

__global__ void dinv_kernel() {
    int i = blockIdx.x * blockDim.x + threadIdx.x;
    if (i < NN) g_dinv[i] = rsqrtf((float)(g_deg[i] + 1)); // +1 self loop
}

// ---------------- layer-1 GEMM: g1 = dinv * (x @ W1) -----------------------
// 16 nodes per block; x tile and W1 staged in shared; thread = (node, col).
__global__ void __launch_bounds__(256) mm1_kernel(const float* __restrict__ x,
                                                  const float* __restrict__ W1) {
    __shared__ float Ws[128 * 16];
    __shared__ float xs[16 * 128];
    int t = threadIdx.x;
    for (int i = t; i < 2048; i += 256) Ws[i] = W1[i];
    long long base = (long long)blockIdx.x * 16;              // first node
    for (int i = t; i < 2048; i += 256) xs[i] = x[base * 128 + i];
    __syncthreads();
    int r = t >> 4, j = t & 15;
    const float* xr = &xs[r * 128];
    float acc = 0.f;
#pragma unroll
    for (int k = 0; k < 128; k++) acc += xr[k] * Ws[k * 16 + j];
    int n = (int)base + r;
    g_g1[n * 16 + j] = g_dinv[n] * acc;
}

// ---------------- edge scatter, layer 1: acc1[dst] += g1[src] --------------
// 4 threads per edge, one float4 each; index loads broadcast within the quad.
__global__ void __launch_bounds__(256) scatter1_kernel(const int* __restrict__ e) {
    long long gid = (long long)blockIdx.x * blockDim.x + threadIdx.x;
    if (gid >= 4LL * NE) return;
    int ei = (int)(gid >> 2), p = (int)(gid & 3);
    int is64 = g_is64;
    long long st = is64 ? 2 : 1;
    int s = e[(long long)ei * st];
    int d = e[(is64 ? 2LL * NE : (long long)NE) + (long long)ei * st];
    float4 v = __ldg((const float4*)&g_g1[(long long)s * 16 + p * 4]);
    red4(&g_acc1[(long long)d * 16 + p * 4], v);
}

// ---------------- relu epilogue + layer-2 GEMM -----------------------------
// out1 = dinv*(acc1+g1)+b1 ; t = relu(out1) ; g2 = dinv*(t @ W2)
// 8 nodes per block; thread = (node, out-col of 32).
__global__ void __launch_bounds__(256) fin1_kernel(const float* __restrict__ W2,
                                                   const float* __restrict__ b1) {
    __shared__ float W2s[16 * 32];
    __shared__ float ts[8 * 16];
    int t = threadIdx.x;
    for (int i = t; i < 512; i += 256) W2s[i] = W2[i];
    int base = blockIdx.x * 8;
    if (t < 128) {
        int r = t >> 4, l = t & 15;
        int n = base + r;
        float a = g_acc1[n * 16 + l] + g_g1[n * 16 + l];
        float v = g_dinv[n] * a + b1[l];
        ts[t] = v > 0.f ? v : 0.f;
    }
    __syncthreads();
    int r = t >> 5, j = t & 31;
    int n = base + r;
    float acc = 0.f;
#pragma unroll
    for (int l = 0; l < 16; l++) acc += ts[r * 16 + l] * W2s[l * 32 + j];
    g_g2[n * 32 + j] = g_dinv[n] * acc;
}

// ---------------- edge scatter, layer 2: out[dst] += g2[src] ---------------
// 8 threads per edge, one float4 each; accumulate directly into d_out.
__global__ void __launch_bounds__(256) scatter2_kernel(const int* __restrict__ e,
                                                       float* __restrict__ out) {
    long long gid = (long long)blockIdx.x * blockDim.x + threadIdx.x;
    if (gid >= 8LL * NE) return;
    int ei = (int)(gid >> 3), p = (int)(gid & 7);
    int is64 = g_is64;
    long long st = is64 ? 2 : 1;
    int s = e[(long long)ei * st];
    int d = e[(is64 ? 2LL * NE : (long long)NE) + (long long)ei * st];
    float4 v = __ldg((const float4*)&g_g2[(long long)s * 32 + p * 4]);
    red4(&out[(long long)d * 32 + p * 4], v);
}

// ---------------- final epilogue: out = dinv*(acc2 + g2) + b2 --------------
__global__ void fin2_kernel(float* __restrict__ out,
                            const float* __restrict__ b2) {
    int i = blockIdx.x * blockDim.x + threadIdx.x;
    if (i >= NN * 32) return;
    int n = i >> 5;
    out[i] = g_dinv[n] * (out[i] + g_g2[i]) + b2[i & 31];
}

// ---------------- launch ---------------------------------------------------
extern "C" void kernel_launch(void* const* d_in, const int* in_sizes, int n_in,
                              void* d_out, int out_size) {
    const float* x  = (const float*)d_in[0];
    const int*   e  = (const int*)  d_in[1];
    const float* W1 = (const float*)d_in[2];
    const float* b1 = (const float*)d_in[3];
    const float* W2 = (const float*)d_in[4];
    const float* b2 = (const float*)d_in[5];
    float* out = (float*)d_out;

    detect_kernel<<<1, 1024>>>(e);
    zero_kernel<<<(NN * 32 + 255) / 256, 256>>>(out);
    deg_kernel<<<(NE + 255) / 256, 256>>>(e);
    dinv_kernel<<<(NN + 255) / 256, 256>>>();
    mm1_kernel<<<NN / 16, 256>>>(x, W1);
    scatter1_kernel<<<(int)((4LL * NE + 255) / 256), 256>>>(e);
    fin1_kernel<<<NN / 8, 256>>>(W2, b1);
    scatter2_kernel<<<(int)((8LL * NE + 255) / 256), 256>>>(e, out);
    fin2_kernel<<<(NN * 32 + 255) / 256, 256>>>(out, b2);
}

// round 3
// speedup vs baseline: 1.1779x; 1.1779x over previous
#include <cuda_runtime.h>

#define NN 100000
#define NE 3200000

// ---------------- scratch (static __device__ arrays; no allocation) --------
__device__ int   g_is64;
__device__ int   g_src [NE];        // compacted int32 src
__device__ int   g_dst [NE];        // compacted int32 dst
__device__ int   g_deg [NN];
__device__ float g_dinv[NN];
__device__ float g_g1  [NN * 16];   // dinv * (x @ W1)
__device__ float g_acc1[NN * 16];   // edge-aggregated g1
__device__ float g_t   [NN * 16];   // dinv * relu(out1)
__device__ float g_acc2[NN * 16];   // edge-aggregated g_t

// vectorized fp32 reduction to global (sm_90+): 4 floats, no return value
__device__ __forceinline__ void red4(float* a, float4 v) {
    asm volatile("red.global.add.v4.f32 [%0], {%1,%2,%3,%4};"
                 :: "l"(a), "f"(v.x), "f"(v.y), "f"(v.z), "f"(v.w)
                 : "memory");
}

// ---------------- dtype detection -----------------------------------------
// edge_index values are in [0, 100000); if stored as int64 (little-endian),
// every odd int32 word is 0. For int32 data, 4096 random values in
// [0,100000) being all < 65536 has probability ~(0.655)^4096 ~= 0.
__global__ void detect_kernel(const int* __restrict__ e) {
    __shared__ int flag;
    if (threadIdx.x == 0) flag = 0;
    __syncthreads();
    int v = 0;
    for (int i = threadIdx.x; i < 4096; i += 1024) v |= e[2 * i + 1];
    if (v) atomicOr(&flag, 1);
    __syncthreads();
    if (threadIdx.x == 0) g_is64 = (flag == 0);
}

// ---------------- zero scratch ---------------------------------------------
__global__ void zero_kernel() {
    int i = blockIdx.x * blockDim.x + threadIdx.x;
    if (i < NN * 16) { g_acc1[i] = 0.f; g_acc2[i] = 0.f; }
    if (i < NN)      g_deg[i] = 0;
}

// ---------------- fused edge compaction (->int32) + degree -----------------
__global__ void __launch_bounds__(256) compact_deg_kernel(const int* __restrict__ e) {
    int i = blockIdx.x * blockDim.x + threadIdx.x;
    if (i >= NE) return;
    int s, d;
    if (g_is64) {
        s = e[2LL * i];
        d = e[2LL * NE + 2LL * i];
    } else {
        s = e[i];
        d = e[NE + i];
    }
    g_src[i] = s;
    g_dst[i] = d;
    atomicAdd(&g_deg[d], 1);
}

__global__ void dinv_kernel() {
    int i = blockIdx.x * blockDim.x + threadIdx.x;
    if (i < NN) g_dinv[i] = rsqrtf((float)(g_deg[i] + 1)); // +1 self loop
}

// ---------------- layer-1 GEMM: g1 = dinv * (x @ W1) -----------------------
// 16 nodes per block; x tile and W1 staged in shared; thread = (node, col).
__global__ void __launch_bounds__(256) mm1_kernel(const float* __restrict__ x,
                                                  const float* __restrict__ W1) {
    __shared__ float Ws[128 * 16];
    __shared__ float xs[16 * 128];
    int t = threadIdx.x;
    for (int i = t; i < 2048; i += 256) Ws[i] = W1[i];
    long long base = (long long)blockIdx.x * 16;              // first node
    for (int i = t; i < 2048; i += 256) xs[i] = x[base * 128 + i];
    __syncthreads();
    int r = t >> 4, j = t & 15;
    const float* xr = &xs[r * 128];
    float acc = 0.f;
#pragma unroll
    for (int k = 0; k < 128; k++) acc += xr[k] * Ws[k * 16 + j];
    int n = (int)base + r;
    g_g1[n * 16 + j] = g_dinv[n] * acc;
}

// ---------------- edge scatter (F=16): acc[dst] += src_feat[src] -----------
// 4 threads per edge, one float4 each; index loads broadcast within the quad.
__global__ void __launch_bounds__(256) scatter16_kernel(const float* __restrict__ feat,
                                                        float* __restrict__ acc) {
    long long gid = (long long)blockIdx.x * blockDim.x + threadIdx.x;
    if (gid >= 4LL * NE) return;
    int ei = (int)(gid >> 2), p = (int)(gid & 3);
    int s = g_src[ei];
    int d = g_dst[ei];
    float4 v = __ldg((const float4*)&feat[(long long)s * 16 + p * 4]);
    red4(&acc[(long long)d * 16 + p * 4], v);
}

// ---------------- layer-1 epilogue (elementwise): t = dinv*relu(out1) ------
// out1 = dinv*(acc1 + g1) + b1
__global__ void fin1_kernel(const float* __restrict__ b1) {
    int i = blockIdx.x * blockDim.x + threadIdx.x;
    if (i >= NN * 16) return;
    int n = i >> 4;
    float di = g_dinv[n];
    float v = di * (g_acc1[i] + g_g1[i]) + b1[i & 15];
    g_t[i] = v > 0.f ? di * v : 0.f;
}

// ---------------- final: out = (dinv*(acc2 + t)) @ W2 + b2 -----------------
// 8 nodes per block; thread = (node, out-col of 32).
__global__ void __launch_bounds__(256) fin2_kernel(float* __restrict__ out,
                                                   const float* __restrict__ W2,
                                                   const float* __restrict__ b2) {
    __shared__ float W2s[16 * 32];
    __shared__ float us[8 * 16];
    int t = threadIdx.x;
    for (int i = t; i < 512; i += 256) W2s[i] = W2[i];
    int base = blockIdx.x * 8;
    if (t < 128) {
        int r = t >> 4;
        int n = base + r;
        int i = n * 16 + (t & 15);
        us[t] = g_dinv[n] * (g_acc2[i] + g_t[i]);
    }
    __syncthreads();
    int r = t >> 5, j = t & 31;
    float acc = b2[j];
#pragma unroll
    for (int l = 0; l < 16; l++) acc += us[r * 16 + l] * W2s[l * 32 + j];
    out[(base + r) * 32 + j] = acc;
}

// ---------------- launch ---------------------------------------------------
extern "C" void kernel_launch(void* const* d_in, const int* in_sizes, int n_in,
                              void* d_out, int out_size) {
    const float* x  = (const float*)d_in[0];
    const int*   e  = (const int*)  d_in[1];
    const float* W1 = (const float*)d_in[2];
    const float* b1 = (const float*)d_in[3];
    const float* W2 = (const float*)d_in[4];
    const float* b2 = (const float*)d_in[5];
    float* out = (float*)d_out;

    float* d_g1   = nullptr; float* d_acc1 = nullptr;
    float* d_t    = nullptr; float* d_acc2 = nullptr;
    cudaGetSymbolAddress((void**)&d_g1,   g_g1);
    cudaGetSymbolAddress((void**)&d_acc1, g_acc1);
    cudaGetSymbolAddress((void**)&d_t,    g_t);
    cudaGetSymbolAddress((void**)&d_acc2, g_acc2);

    detect_kernel<<<1, 1024>>>(e);
    zero_kernel<<<(NN * 16 + 255) / 256, 256>>>();
    compact_deg_kernel<<<(NE + 255) / 256, 256>>>(e);
    dinv_kernel<<<(NN + 255) / 256, 256>>>();
    mm1_kernel<<<NN / 16, 256>>>(x, W1);
    scatter16_kernel<<<(int)((4LL * NE + 255) / 256), 256>>>(d_g1, d_acc1);
    fin1_kernel<<<(NN * 16 + 255) / 256, 256>>>(b1);
    scatter16_kernel<<<(int)((4LL * NE + 255) / 256), 256>>>(d_t, d_acc2);
    fin2_kernel<<<NN / 8, 256>>>(out, W2, b2);
}

// round 5
// speedup vs baseline: 1.2249x; 1.0399x over previous
#include <cuda_runtime.h>

#define NN 100000
#define NE 3200000
#define NB_SCAN 98   // ceil(NN / 1024)

// ---------------- scratch (static __device__ arrays; no allocation) --------
__device__ int   g_is64;
__device__ int   g_src [NE];        // compacted int32 src
__device__ int   g_dst [NE];        // compacted int32 dst
__device__ int   g_eidx[NE];        // CSR: src ids grouped by dst
__device__ int   g_deg [NN];
__device__ int   g_off [NN];        // CSR row start
__device__ int   g_cur [NN];        // fill cursors
__device__ int   g_bsum[NB_SCAN];
__device__ float g_dinv[NN];
__device__ float g_g1  [NN * 16];   // dinv * (x @ W1)
__device__ float g_t   [NN * 16];   // dinv * relu(out1)

// ---------------- dtype detect + zero degrees ------------------------------
// edge_index values are in [0,100000); if int64 (LE), every odd word is 0.
__global__ void detect_zero_kernel(const int* __restrict__ e) {
    __shared__ int flag;
    if (threadIdx.x == 0) flag = 0;
    __syncthreads();
    int v = 0;
    for (int i = threadIdx.x; i < 4096; i += 1024) v |= e[2 * i + 1];
    if (v) atomicOr(&flag, 1);
    for (int i = threadIdx.x; i < NN; i += 1024) g_deg[i] = 0;
    __syncthreads();
    if (threadIdx.x == 0) g_is64 = (flag == 0);
}

// ---------------- edge compaction (->int32) + degree -----------------------
__global__ void __launch_bounds__(256) compact_deg_kernel(const int* __restrict__ e) {
    int i = blockIdx.x * blockDim.x + threadIdx.x;
    if (i >= NE) return;
    int s, d;
    if (g_is64) { s = e[2LL * i];  d = e[2LL * NE + 2LL * i]; }
    else        { s = e[i];        d = e[NE + i]; }
    g_src[i] = s;
    g_dst[i] = d;
    atomicAdd(&g_deg[d], 1);
}

// ---------------- prefix scan of degrees (3 stages) ------------------------
__global__ void __launch_bounds__(1024) scan1_kernel() {
    __shared__ int sm[1024];
    int t = threadIdx.x, n = blockIdx.x * 1024 + t;
    int d = (n < NN) ? g_deg[n] : 0;
    sm[t] = d;
    __syncthreads();
    for (int off = 1; off < 1024; off <<= 1) {
        int v = (t >= off) ? sm[t - off] : 0;
        __syncthreads();
        sm[t] += v;
        __syncthreads();
    }
    if (n < NN) g_off[n] = sm[t] - d;          // exclusive within block
    if (t == 1023) g_bsum[blockIdx.x] = sm[1023];
}

// parallel exclusive scan of the 98 block sums (one block, shared memory)
__global__ void __launch_bounds__(128) scan2_kernel() {
    __shared__ int sm[128];
    int t = threadIdx.x;
    int v = (t < NB_SCAN) ? g_bsum[t] : 0;
    sm[t] = v;
    __syncthreads();
    for (int off = 1; off < 128; off <<= 1) {
        int u = (t >= off) ? sm[t - off] : 0;
        __syncthreads();
        sm[t] += u;
        __syncthreads();
    }
    if (t < NB_SCAN) g_bsum[t] = sm[t] - v;    // exclusive
}

__global__ void scan3_dinv_kernel() {
    int n = blockIdx.x * blockDim.x + threadIdx.x;
    if (n >= NN) return;
    int o = g_off[n] + g_bsum[n >> 10];
    g_off[n] = o;
    g_cur[n] = o;
    g_dinv[n] = rsqrtf((float)(g_deg[n] + 1));  // +1 self loop
}

// ---------------- CSR fill --------------------------------------------------
__global__ void __launch_bounds__(256) fill_kernel() {
    int i = blockIdx.x * blockDim.x + threadIdx.x;
    if (i >= NE) return;
    int pos = atomicAdd(&g_cur[g_dst[i]], 1);
    g_eidx[pos] = g_src[i];
}

// ---------------- layer-1 GEMM: g1 = dinv * (x @ W1) -----------------------
__global__ void __launch_bounds__(256) mm1_kernel(const float* __restrict__ x,
                                                  const float* __restrict__ W1) {
    __shared__ float Ws[128 * 16];
    __shared__ float xs[16 * 128];
    int t = threadIdx.x;
    for (int i = t; i < 2048; i += 256) Ws[i] = W1[i];
    long long base = (long long)blockIdx.x * 16;
    for (int i = t; i < 2048; i += 256) xs[i] = x[base * 128 + i];
    __syncthreads();
    int r = t >> 4, j = t & 15;
    const float* xr = &xs[r * 128];
    float acc = 0.f;
#pragma unroll
    for (int k = 0; k < 128; k++) acc += xr[k] * Ws[k * 16 + j];
    int n = (int)base + r;
    g_g1[n * 16 + j] = g_dinv[n] * acc;
}

// ---------------- warp-per-node CSR accumulate (F=16) ----------------------
// lane = eg*4 + p : quad eg handles one edge per iter, phase p its float4.
// Next-index prefetch overlaps the idx load with the current feature load.
// After xor-reduction every lane holds the total for its phase p.
__device__ __forceinline__ float4 warp_gather16(const float* __restrict__ feat,
                                                int node, int eg, int p) {
    int start = g_off[node], deg = g_deg[node];
    float4 acc = make_float4(0.f, 0.f, 0.f, 0.f);
    int i = eg;
    int s = (i < deg) ? __ldg(&g_eidx[start + i]) : 0;
    while (i < deg) {
        int j = i + 8;
        int s2 = (j < deg) ? __ldg(&g_eidx[start + j]) : 0;
        float4 v = __ldg((const float4*)&feat[s * 16 + p * 4]);
        acc.x += v.x; acc.y += v.y; acc.z += v.z; acc.w += v.w;
        s = s2; i = j;
    }
#pragma unroll
    for (int m = 16; m >= 4; m >>= 1) {
        acc.x += __shfl_xor_sync(0xffffffffu, acc.x, m);
        acc.y += __shfl_xor_sync(0xffffffffu, acc.y, m);
        acc.z += __shfl_xor_sync(0xffffffffu, acc.z, m);
        acc.w += __shfl_xor_sync(0xffffffffu, acc.w, m);
    }
    return acc;
}

// ---------------- gather layer 1 + fused relu epilogue ---------------------
// t = dinv * relu( dinv*(agg + g1_self) + b1 )
__global__ void __launch_bounds__(256) gather1_kernel(const float* __restrict__ b1) {
    int wid = (blockIdx.x * 256 + threadIdx.x) >> 5;   // node id (grid exact)
    int lane = threadIdx.x & 31, eg = lane >> 2, p = lane & 3;
    float4 acc = warp_gather16(g_g1, wid, eg, p);
    if (eg == 0) {
        float4 self = *(const float4*)&g_g1[wid * 16 + p * 4];
        float di = g_dinv[wid];
        float4 o;
        o.x = di * (acc.x + self.x) + b1[p * 4 + 0];
        o.y = di * (acc.y + self.y) + b1[p * 4 + 1];
        o.z = di * (acc.z + self.z) + b1[p * 4 + 2];
        o.w = di * (acc.w + self.w) + b1[p * 4 + 3];
        o.x = o.x > 0.f ? di * o.x : 0.f;
        o.y = o.y > 0.f ? di * o.y : 0.f;
        o.z = o.z > 0.f ? di * o.z : 0.f;
        o.w = o.w > 0.f ? di * o.w : 0.f;
        *(float4*)&g_t[wid * 16 + p * 4] = o;
    }
}

// ---------------- gather layer 2 + fused W2 GEMM + bias --------------------
// u = dinv*(agg + t_self);  out = u @ W2 + b2   (in-warp 16x32 GEMM)
__global__ void __launch_bounds__(256) gather2_kernel(float* __restrict__ out,
                                                      const float* __restrict__ W2,
                                                      const float* __restrict__ b2) {
    __shared__ float W2s[16 * 32];
    for (int i = threadIdx.x; i < 512; i += 256) W2s[i] = W2[i];
    __syncthreads();
    int wid = (blockIdx.x * 256 + threadIdx.x) >> 5;
    int lane = threadIdx.x & 31, eg = lane >> 2, p = lane & 3;
    float4 acc = warp_gather16(g_t, wid, eg, p);
    float4 self = *(const float4*)&g_t[wid * 16 + p * 4];
    float di = g_dinv[wid];
    float4 u4;
    u4.x = di * (acc.x + self.x);
    u4.y = di * (acc.y + self.y);
    u4.z = di * (acc.z + self.z);
    u4.w = di * (acc.w + self.w);
    // collect full u[16] into every lane via shfl from lanes 0..3
    float u[16];
#pragma unroll
    for (int l = 0; l < 16; l++) {
        float c = ((l & 3) == 0) ? u4.x : ((l & 3) == 1) ? u4.y
                : ((l & 3) == 2) ? u4.z : u4.w;
        u[l] = __shfl_sync(0xffffffffu, c, l >> 2);
    }
    float o = b2[lane];
#pragma unroll
    for (int l = 0; l < 16; l++) o += u[l] * W2s[l * 32 + lane];
    out[wid * 32 + lane] = o;
}

// ---------------- launch ---------------------------------------------------
extern "C" void kernel_launch(void* const* d_in, const int* in_sizes, int n_in,
                              void* d_out, int out_size) {
    const float* x  = (const float*)d_in[0];
    const int*   e  = (const int*)  d_in[1];
    const float* W1 = (const float*)d_in[2];
    const float* b1 = (const float*)d_in[3];
    const float* W2 = (const float*)d_in[4];
    const float* b2 = (const float*)d_in[5];
    float* out = (float*)d_out;

    detect_zero_kernel<<<1, 1024>>>(e);
    compact_deg_kernel<<<(NE + 255) / 256, 256>>>(e);
    scan1_kernel<<<NB_SCAN, 1024>>>();
    scan2_kernel<<<1, 128>>>();
    scan3_dinv_kernel<<<(NN + 255) / 256, 256>>>();
    fill_kernel<<<(NE + 255) / 256, 256>>>();
    mm1_kernel<<<NN / 16, 256>>>(x, W1);
    gather1_kernel<<<NN / 8, 256>>>(b1);
    gather2_kernel<<<NN / 8, 256>>>(out, W2, b2);
}